// round 8
// baseline (speedup 1.0000x reference)
#include <cuda_runtime.h>
#include <cuda_fp16.h>
#include <cstdint>

#define NMAX 100000
#define EMAX 2000000
#define D    64

// ---------------------------------------------------------------------------
// Scratch (device globals — no allocation allowed)
// ---------------------------------------------------------------------------
__device__ int     g_deg[NMAX];
__device__ int     g_off[NMAX + 1];
__device__ int     g_cursor[NMAX];
__device__ float   g_invdeg[NMAX];
__device__ int     g_csr[EMAX];
__device__ float   g_agg[NMAX * D];
__device__ float   g_h[NMAX * D];
__device__ __half2 g_half[NMAX * 32];   // fp16 mirror of current features
__device__ int     g_bsum[64];

__device__ __forceinline__ uint32_t cvt_tf32(float f) {
    uint32_t r;
    asm("cvt.rna.tf32.f32 %0, %1;" : "=r"(r) : "f"(f));
    return r;
}

// ---------------------------------------------------------------------------
// fp32 -> fp16 mirror convert (x at layer 0)
// ---------------------------------------------------------------------------
__global__ void to_half_kernel(const float4* __restrict__ in, int nq) {
    int i = blockIdx.x * blockDim.x + threadIdx.x;
    if (i < nq) {
        float4 v = __ldg(&in[i]);
        g_half[2 * i]     = __floats2half2_rn(v.x, v.y);
        g_half[2 * i + 1] = __floats2half2_rn(v.z, v.w);
    }
}

// ---------------------------------------------------------------------------
// CSR build
// ---------------------------------------------------------------------------
__global__ void deg_kernel(const int* __restrict__ dst, int e) {
    int i = blockIdx.x * blockDim.x + threadIdx.x;
    int base = i * 8;
    if (base + 7 < e) {
        int4 a = *reinterpret_cast<const int4*>(dst + base);
        int4 b = *reinterpret_cast<const int4*>(dst + base + 4);
        atomicAdd(&g_deg[a.x], 1); atomicAdd(&g_deg[a.y], 1);
        atomicAdd(&g_deg[a.z], 1); atomicAdd(&g_deg[a.w], 1);
        atomicAdd(&g_deg[b.x], 1); atomicAdd(&g_deg[b.y], 1);
        atomicAdd(&g_deg[b.z], 1); atomicAdd(&g_deg[b.w], 1);
    } else {
        for (int k = base; k < e; k++) atomicAdd(&g_deg[dst[k]], 1);
    }
}

// Phase 1: per-block (2048 nodes) sums
__global__ void scan_sum(int n) {
    __shared__ int sh[256];
    int b = blockIdx.x, t = threadIdx.x;
    int base = b * 2048 + t * 8;
    int s = 0;
    for (int i = 0; i < 8; i++) { int nd = base + i; if (nd < n) s += g_deg[nd]; }
    sh[t] = s; __syncthreads();
    for (int off = 128; off > 0; off >>= 1) {
        if (t < off) sh[t] += sh[t + off];
        __syncthreads();
    }
    if (t == 0) g_bsum[b] = sh[0];
}

// Phase 2: block-offset scan inlined + apply (off/cursor/invdeg)
__global__ void scan_apply(int nb, int n, int e) {
    __shared__ int sbs[64];
    __shared__ int sh[256];
    int b = blockIdx.x, t = threadIdx.x;

    if (t < 64) sbs[t] = (t < nb) ? g_bsum[t] : 0;
    __syncthreads();
    for (int off = 1; off < 64; off <<= 1) {
        int x = 0;
        if (t < 64) { x = sbs[t]; if (t >= off) x += sbs[t - off]; }
        __syncthreads();
        if (t < 64) sbs[t] = x;
        __syncthreads();
    }
    int block_off = (b == 0) ? 0 : sbs[b - 1];

    int base = b * 2048 + t * 8;
    int d[8]; int s = 0;
    for (int i = 0; i < 8; i++) {
        int nd = base + i;
        d[i] = (nd < n) ? g_deg[nd] : 0;
        s += d[i];
    }
    sh[t] = s; __syncthreads();
    for (int off = 1; off < 256; off <<= 1) {
        int x = sh[t];
        if (t >= off) x += sh[t - off];
        __syncthreads(); sh[t] = x; __syncthreads();
    }
    int run = block_off + sh[t] - s;
    for (int i = 0; i < 8; i++) {
        int nd = base + i;
        if (nd < n) {
            g_off[nd] = run;
            g_cursor[nd] = run;
            g_invdeg[nd] = 1.0f / fmaxf((float)d[i], 1.0f);
            run += d[i];
        }
    }
    if (b == 0 && t == 0) g_off[n] = e;
}

__global__ void fill_kernel(const int* __restrict__ src,
                            const int* __restrict__ dst, int e) {
    int i = blockIdx.x * blockDim.x + threadIdx.x;
    int base = i * 8;
    if (base + 7 < e) {
        int4 da = *reinterpret_cast<const int4*>(dst + base);
        int4 db = *reinterpret_cast<const int4*>(dst + base + 4);
        int4 sa = *reinterpret_cast<const int4*>(src + base);
        int4 sb = *reinterpret_cast<const int4*>(src + base + 4);
        int p0 = atomicAdd(&g_cursor[da.x], 1);
        int p1 = atomicAdd(&g_cursor[da.y], 1);
        int p2 = atomicAdd(&g_cursor[da.z], 1);
        int p3 = atomicAdd(&g_cursor[da.w], 1);
        int p4 = atomicAdd(&g_cursor[db.x], 1);
        int p5 = atomicAdd(&g_cursor[db.y], 1);
        int p6 = atomicAdd(&g_cursor[db.z], 1);
        int p7 = atomicAdd(&g_cursor[db.w], 1);
        g_csr[p0] = sa.x; g_csr[p1] = sa.y; g_csr[p2] = sa.z; g_csr[p3] = sa.w;
        g_csr[p4] = sb.x; g_csr[p5] = sb.y; g_csr[p6] = sb.z; g_csr[p7] = sb.w;
    } else {
        for (int k = base; k < e; k++) {
            int p = atomicAdd(&g_cursor[dst[k]], 1);
            g_csr[p] = src[k];
        }
    }
}

// ---------------------------------------------------------------------------
// Aggregation: warp per node, fp16 gather (128B/row), fp32 accumulate
// ---------------------------------------------------------------------------
__global__ __launch_bounds__(256) void agg_kernel(int n) {
    int node = blockIdx.x * 8 + (threadIdx.x >> 5);
    int lane = threadIdx.x & 31;
    if (node >= n) return;
    const __half2* h2 = g_half;
    int beg = g_off[node];
    int end = g_off[node + 1];
    float2 acc = make_float2(0.f, 0.f);
    for (int base = beg; base < end; base += 32) {
        int idx = base + lane;
        int s = (idx < end) ? __ldg(&g_csr[idx]) : 0;
        int cnt = min(32, end - base);
        int k = 0;
        for (; k + 8 <= cnt; k += 8) {
            int s0 = __shfl_sync(0xffffffffu, s, k);
            int s1 = __shfl_sync(0xffffffffu, s, k + 1);
            int s2 = __shfl_sync(0xffffffffu, s, k + 2);
            int s3 = __shfl_sync(0xffffffffu, s, k + 3);
            int s4 = __shfl_sync(0xffffffffu, s, k + 4);
            int s5 = __shfl_sync(0xffffffffu, s, k + 5);
            int s6 = __shfl_sync(0xffffffffu, s, k + 6);
            int s7 = __shfl_sync(0xffffffffu, s, k + 7);
            float2 v0 = __half22float2(__ldg(&h2[(size_t)s0 * 32 + lane]));
            float2 v1 = __half22float2(__ldg(&h2[(size_t)s1 * 32 + lane]));
            float2 v2 = __half22float2(__ldg(&h2[(size_t)s2 * 32 + lane]));
            float2 v3 = __half22float2(__ldg(&h2[(size_t)s3 * 32 + lane]));
            float2 v4 = __half22float2(__ldg(&h2[(size_t)s4 * 32 + lane]));
            float2 v5 = __half22float2(__ldg(&h2[(size_t)s5 * 32 + lane]));
            float2 v6 = __half22float2(__ldg(&h2[(size_t)s6 * 32 + lane]));
            float2 v7 = __half22float2(__ldg(&h2[(size_t)s7 * 32 + lane]));
            acc.x += ((v0.x + v1.x) + (v2.x + v3.x)) + ((v4.x + v5.x) + (v6.x + v7.x));
            acc.y += ((v0.y + v1.y) + (v2.y + v3.y)) + ((v4.y + v5.y) + (v6.y + v7.y));
        }
        for (; k + 4 <= cnt; k += 4) {
            int s0 = __shfl_sync(0xffffffffu, s, k);
            int s1 = __shfl_sync(0xffffffffu, s, k + 1);
            int s2 = __shfl_sync(0xffffffffu, s, k + 2);
            int s3 = __shfl_sync(0xffffffffu, s, k + 3);
            float2 v0 = __half22float2(__ldg(&h2[(size_t)s0 * 32 + lane]));
            float2 v1 = __half22float2(__ldg(&h2[(size_t)s1 * 32 + lane]));
            float2 v2 = __half22float2(__ldg(&h2[(size_t)s2 * 32 + lane]));
            float2 v3 = __half22float2(__ldg(&h2[(size_t)s3 * 32 + lane]));
            acc.x += (v0.x + v1.x) + (v2.x + v3.x);
            acc.y += (v0.y + v1.y) + (v2.y + v3.y);
        }
        for (; k < cnt; k++) {
            int sk = __shfl_sync(0xffffffffu, s, k);
            float2 v = __half22float2(__ldg(&h2[(size_t)sk * 32 + lane]));
            acc.x += v.x; acc.y += v.y;
        }
    }
    float id = g_invdeg[node];
    reinterpret_cast<float2*>(g_agg)[(size_t)node * 32 + lane] =
        make_float2(acc.x * id, acc.y * id);
}

// ---------------------------------------------------------------------------
// tf32 mma.sync linear: out = act( concat(hin, agg) @ W + b )
// Tile = 64 nodes x 64 cols, K = 128 (16 k8 steps). 8 warps; W in registers.
// K-slot remap: hw slot (tg,hi) <- logical k=2*tg+hi for A and B -> LDS.64.
// WRITE_HALF: also write fp16 mirror of output (layer 0 -> layer 1 gather).
// ---------------------------------------------------------------------------
#define A_STRIDE 132

__device__ __forceinline__ void mma_tf32(float& c0, float& c1, float& c2, float& c3,
                                         uint32_t a0, uint32_t a1, uint32_t a2, uint32_t a3,
                                         uint32_t b0, uint32_t b1) {
    asm volatile("mma.sync.aligned.m16n8k8.row.col.f32.tf32.tf32.f32 "
                 "{%0,%1,%2,%3}, {%4,%5,%6,%7}, {%8,%9}, {%0,%1,%2,%3};"
                 : "+f"(c0), "+f"(c1), "+f"(c2), "+f"(c3)
                 : "r"(a0), "r"(a1), "r"(a2), "r"(a3), "r"(b0), "r"(b1));
}

template <bool RELU, bool WRITE_HALF>
__global__ __launch_bounds__(256) void linear_mma(
    const float4* __restrict__ hin4, const float4* __restrict__ agg4,
    const float* __restrict__ W, const float* __restrict__ bias,
    float* __restrict__ out, int n)
{
    __shared__ float As[64 * A_STRIDE];   // 33.8 KB

    int tid = threadIdx.x;
    int wid = tid >> 5, lane = tid & 31;
    int g = lane >> 2, tg = lane & 3;
    int wrow = (wid >> 2) * 32;
    int wcol = (wid & 3) * 16;

    uint32_t Bf[2][16][2];
    #pragma unroll
    for (int t = 0; t < 2; t++) {
        int ncol = wcol + t * 8 + g;
        #pragma unroll
        for (int s = 0; s < 16; s++) {
            Bf[t][s][0] = cvt_tf32(__ldg(&W[(s * 8 + 2 * tg)     * 64 + ncol]));
            Bf[t][s][1] = cvt_tf32(__ldg(&W[(s * 8 + 2 * tg + 1) * 64 + ncol]));
        }
    }
    float bs0[2], bs1[2];
    #pragma unroll
    for (int t = 0; t < 2; t++) {
        bs0[t] = __ldg(&bias[wcol + t * 8 + 2 * tg]);
        bs1[t] = __ldg(&bias[wcol + t * 8 + 2 * tg + 1]);
    }

    int ntiles = (n + 63) >> 6;
    for (int tile = blockIdx.x; tile < ntiles; tile += gridDim.x) {
        __syncthreads();
        #pragma unroll
        for (int r = 0; r < 8; r++) {
            int idx = tid + 256 * r;
            int row = idx >> 5, q = idx & 31;
            int node = tile * 64 + row;
            float4 v = make_float4(0.f, 0.f, 0.f, 0.f);
            if (node < n)
                v = (q < 16) ? __ldg(&hin4[(size_t)node * 16 + q])
                             : __ldg(&agg4[(size_t)node * 16 + q - 16]);
            uint32_t c0 = cvt_tf32(v.x), c1 = cvt_tf32(v.y);
            uint32_t c2 = cvt_tf32(v.z), c3 = cvt_tf32(v.w);
            uint4* p = reinterpret_cast<uint4*>(&As[row * A_STRIDE + q * 4]);
            *p = make_uint4(c0, c1, c2, c3);
        }
        __syncthreads();

        float c0[2][2], c1[2][2], c2[2][2], c3[2][2];
        #pragma unroll
        for (int m = 0; m < 2; m++)
            #pragma unroll
            for (int t = 0; t < 2; t++) {
                c0[m][t] = bs0[t]; c1[m][t] = bs1[t];
                c2[m][t] = bs0[t]; c3[m][t] = bs1[t];
            }

        #pragma unroll
        for (int s = 0; s < 16; s++) {
            int col = s * 8 + 2 * tg;
            #pragma unroll
            for (int m = 0; m < 2; m++) {
                int r0 = wrow + m * 16 + g;
                uint2 lo = *reinterpret_cast<const uint2*>(&As[r0 * A_STRIDE + col]);
                uint2 hi = *reinterpret_cast<const uint2*>(&As[(r0 + 8) * A_STRIDE + col]);
                #pragma unroll
                for (int t = 0; t < 2; t++)
                    mma_tf32(c0[m][t], c1[m][t], c2[m][t], c3[m][t],
                             lo.x, hi.x, lo.y, hi.y, Bf[t][s][0], Bf[t][s][1]);
            }
        }

        #pragma unroll
        for (int m = 0; m < 2; m++) {
            int row0 = tile * 64 + wrow + m * 16 + g;
            #pragma unroll
            for (int t = 0; t < 2; t++) {
                int col = wcol + t * 8 + 2 * tg;
                float2 lo = make_float2(c0[m][t], c1[m][t]);
                float2 hi = make_float2(c2[m][t], c3[m][t]);
                if (RELU) {
                    lo.x = fmaxf(lo.x, 0.f); lo.y = fmaxf(lo.y, 0.f);
                    hi.x = fmaxf(hi.x, 0.f); hi.y = fmaxf(hi.y, 0.f);
                }
                if (row0 < n) {
                    *reinterpret_cast<float2*>(&out[(size_t)row0 * 64 + col]) = lo;
                    if (WRITE_HALF)
                        g_half[(size_t)row0 * 32 + (col >> 1)] = __floats2half2_rn(lo.x, lo.y);
                }
                if (row0 + 8 < n) {
                    *reinterpret_cast<float2*>(&out[(size_t)(row0 + 8) * 64 + col]) = hi;
                    if (WRITE_HALF)
                        g_half[(size_t)(row0 + 8) * 32 + (col >> 1)] = __floats2half2_rn(hi.x, hi.y);
                }
            }
        }
    }
}

// ---------------------------------------------------------------------------
extern "C" void kernel_launch(void* const* d_in, const int* in_sizes, int n_in,
                              void* d_out, int out_size) {
    const float* x  = (const float*)d_in[0];          // [N, 64]
    const int*   ei = (const int*)d_in[1];            // [2, E]
    const float* W0 = (const float*)d_in[2];          // [128, 64]
    const float* b0 = (const float*)d_in[3];          // [64]
    const float* W1 = (const float*)d_in[4];          // [128, 64]
    const float* b1 = (const float*)d_in[5];          // [64]
    float*       out = (float*)d_out;                 // [N, 64]

    int n = in_sizes[0] / D;
    int e = in_sizes[1] / 2;
    const int* src = ei;
    const int* dst = ei + e;

    float* hbuf;
    float* aggbuf;
    void*  degp;
    cudaGetSymbolAddress((void**)&hbuf, g_h);
    cudaGetSymbolAddress((void**)&aggbuf, g_agg);
    cudaGetSymbolAddress(&degp, g_deg);

    // --- fp16 mirror of x ---
    int nq = n * 16;
    to_half_kernel<<<(nq + 255) / 256, 256>>>((const float4*)x, nq);

    // --- CSR build ---
    cudaMemsetAsync(degp, 0, (size_t)n * sizeof(int));
    deg_kernel<<<((e + 7) / 8 + 255) / 256, 256>>>(dst, e);
    int nb = (n + 2047) / 2048;
    scan_sum<<<nb, 256>>>(n);
    scan_apply<<<nb, 256>>>(nb, n, e);
    fill_kernel<<<((e + 7) / 8 + 255) / 256, 256>>>(src, dst, e);

    int ntiles = (n + 63) / 64;
    int grid = ntiles < 888 ? ntiles : 888;

    // --- Layer 0 ---
    agg_kernel<<<(n + 7) / 8, 256>>>(n);
    linear_mma<true, true><<<grid, 256>>>(
        (const float4*)x, (const float4*)aggbuf, W0, b0, hbuf, n);

    // --- Layer 1 ---
    agg_kernel<<<(n + 7) / 8, 256>>>(n);
    linear_mma<false, false><<<grid, 256>>>(
        (const float4*)hbuf, (const float4*)aggbuf, W1, b1, out, n);
}

// round 9
// speedup vs baseline: 1.0780x; 1.0780x over previous
#include <cuda_runtime.h>
#include <cuda_bf16.h>
#include <cstdint>

#define NMAX 100000
#define EMAX 2000000
#define D    64

// ---------------------------------------------------------------------------
// Scratch (device globals — no allocation allowed)
// ---------------------------------------------------------------------------
__device__ int   g_deg[NMAX];
__device__ int   g_off[NMAX + 1];
__device__ int   g_cursor[NMAX];
__device__ float g_invdeg[NMAX];
__device__ int   g_csr[EMAX];
__device__ float g_agg[NMAX * D];
__device__ float g_h[NMAX * D];
__device__ int   g_bsum[64];

__device__ __forceinline__ uint32_t cvt_tf32(float f) {
    uint32_t r;
    asm("cvt.rna.tf32.f32 %0, %1;" : "=r"(r) : "f"(f));
    return r;
}

// ---------------------------------------------------------------------------
// CSR build
// ---------------------------------------------------------------------------
__global__ void deg_kernel(const int* __restrict__ dst, int e) {
    int i = blockIdx.x * blockDim.x + threadIdx.x;
    int base = i * 8;
    if (base + 7 < e) {
        int4 a = *reinterpret_cast<const int4*>(dst + base);
        int4 b = *reinterpret_cast<const int4*>(dst + base + 4);
        atomicAdd(&g_deg[a.x], 1); atomicAdd(&g_deg[a.y], 1);
        atomicAdd(&g_deg[a.z], 1); atomicAdd(&g_deg[a.w], 1);
        atomicAdd(&g_deg[b.x], 1); atomicAdd(&g_deg[b.y], 1);
        atomicAdd(&g_deg[b.z], 1); atomicAdd(&g_deg[b.w], 1);
    } else {
        for (int k = base; k < e; k++) atomicAdd(&g_deg[dst[k]], 1);
    }
}

// Phase 1: per-block (2048 nodes) sums
__global__ void scan_sum(int n) {
    __shared__ int sh[256];
    int b = blockIdx.x, t = threadIdx.x;
    int base = b * 2048 + t * 8;
    int s = 0;
    for (int i = 0; i < 8; i++) { int nd = base + i; if (nd < n) s += g_deg[nd]; }
    sh[t] = s; __syncthreads();
    for (int off = 128; off > 0; off >>= 1) {
        if (t < off) sh[t] += sh[t + off];
        __syncthreads();
    }
    if (t == 0) g_bsum[b] = sh[0];
}

// Phase 2: block-offset scan inlined + apply (off/cursor/invdeg)
__global__ void scan_apply(int nb, int n, int e) {
    __shared__ int sbs[64];
    __shared__ int sh[256];
    int b = blockIdx.x, t = threadIdx.x;

    if (t < 64) sbs[t] = (t < nb) ? g_bsum[t] : 0;
    __syncthreads();
    for (int off = 1; off < 64; off <<= 1) {
        int x = 0;
        if (t < 64) { x = sbs[t]; if (t >= off) x += sbs[t - off]; }
        __syncthreads();
        if (t < 64) sbs[t] = x;
        __syncthreads();
    }
    int block_off = (b == 0) ? 0 : sbs[b - 1];

    int base = b * 2048 + t * 8;
    int d[8]; int s = 0;
    for (int i = 0; i < 8; i++) {
        int nd = base + i;
        d[i] = (nd < n) ? g_deg[nd] : 0;
        s += d[i];
    }
    sh[t] = s; __syncthreads();
    for (int off = 1; off < 256; off <<= 1) {
        int x = sh[t];
        if (t >= off) x += sh[t - off];
        __syncthreads(); sh[t] = x; __syncthreads();
    }
    int run = block_off + sh[t] - s;
    for (int i = 0; i < 8; i++) {
        int nd = base + i;
        if (nd < n) {
            g_off[nd] = run;
            g_cursor[nd] = run;
            g_invdeg[nd] = 1.0f / fmaxf((float)d[i], 1.0f);
            run += d[i];
        }
    }
    if (b == 0 && t == 0) g_off[n] = e;
}

__global__ void fill_kernel(const int* __restrict__ src,
                            const int* __restrict__ dst, int e) {
    int i = blockIdx.x * blockDim.x + threadIdx.x;
    int base = i * 8;
    if (base + 7 < e) {
        int4 da = *reinterpret_cast<const int4*>(dst + base);
        int4 db = *reinterpret_cast<const int4*>(dst + base + 4);
        int4 sa = *reinterpret_cast<const int4*>(src + base);
        int4 sb = *reinterpret_cast<const int4*>(src + base + 4);
        int p0 = atomicAdd(&g_cursor[da.x], 1);
        int p1 = atomicAdd(&g_cursor[da.y], 1);
        int p2 = atomicAdd(&g_cursor[da.z], 1);
        int p3 = atomicAdd(&g_cursor[da.w], 1);
        int p4 = atomicAdd(&g_cursor[db.x], 1);
        int p5 = atomicAdd(&g_cursor[db.y], 1);
        int p6 = atomicAdd(&g_cursor[db.z], 1);
        int p7 = atomicAdd(&g_cursor[db.w], 1);
        g_csr[p0] = sa.x; g_csr[p1] = sa.y; g_csr[p2] = sa.z; g_csr[p3] = sa.w;
        g_csr[p4] = sb.x; g_csr[p5] = sb.y; g_csr[p6] = sb.z; g_csr[p7] = sb.w;
    } else {
        for (int k = base; k < e; k++) {
            int p = atomicAdd(&g_cursor[dst[k]], 1);
            g_csr[p] = src[k];
        }
    }
}

// ---------------------------------------------------------------------------
// Aggregation: 2 nodes per warp, 16 lanes per node, float4 row loads.
// Halves neighbor-row LDG instruction count vs warp-per-node float2 and runs
// two independent dependency chains per warp.
// ---------------------------------------------------------------------------
__global__ __launch_bounds__(256) void agg_kernel(const float4* __restrict__ h4, int n) {
    int warp = blockIdx.x * 8 + (threadIdx.x >> 5);
    int half = (threadIdx.x >> 4) & 1;       // node slot within warp
    int l    = threadIdx.x & 15;             // lane within 16-group
    int node = warp * 2 + half;
    if (node >= n) return;
    unsigned mask = 0xFFFFu << (half * 16);

    int beg = g_off[node];
    int end = g_off[node + 1];
    float4 acc = make_float4(0.f, 0.f, 0.f, 0.f);

    for (int base = beg; base < end; base += 16) {
        int idx = base + l;
        int s = (idx < end) ? __ldg(&g_csr[idx]) : 0;
        int cnt = min(16, end - base);
        int k = 0;
        for (; k + 4 <= cnt; k += 4) {
            int s0 = __shfl_sync(mask, s, k,     16);
            int s1 = __shfl_sync(mask, s, k + 1, 16);
            int s2 = __shfl_sync(mask, s, k + 2, 16);
            int s3 = __shfl_sync(mask, s, k + 3, 16);
            float4 v0 = __ldg(&h4[(size_t)s0 * 16 + l]);
            float4 v1 = __ldg(&h4[(size_t)s1 * 16 + l]);
            float4 v2 = __ldg(&h4[(size_t)s2 * 16 + l]);
            float4 v3 = __ldg(&h4[(size_t)s3 * 16 + l]);
            acc.x += (v0.x + v1.x) + (v2.x + v3.x);
            acc.y += (v0.y + v1.y) + (v2.y + v3.y);
            acc.z += (v0.z + v1.z) + (v2.z + v3.z);
            acc.w += (v0.w + v1.w) + (v2.w + v3.w);
        }
        for (; k < cnt; k++) {
            int sk = __shfl_sync(mask, s, k, 16);
            float4 v = __ldg(&h4[(size_t)sk * 16 + l]);
            acc.x += v.x; acc.y += v.y; acc.z += v.z; acc.w += v.w;
        }
    }
    float id = g_invdeg[node];
    acc.x *= id; acc.y *= id; acc.z *= id; acc.w *= id;
    reinterpret_cast<float4*>(g_agg)[(size_t)node * 16 + l] = acc;
}

// ---------------------------------------------------------------------------
// tf32 mma.sync linear: out = act( concat(hin, agg) @ W + b )
// Persistent blocks. Tile = 64 nodes x 64 cols, K = 128 (16 k8 steps).
// 8 warps = 2 row-groups x 4 col-groups; W register-resident per warp.
// K-slot remap: hw slot (tg,hi) <- logical k=2*tg+hi for A and B -> LDS.64.
// ---------------------------------------------------------------------------
#define A_STRIDE 132

__device__ __forceinline__ void mma_tf32(float& c0, float& c1, float& c2, float& c3,
                                         uint32_t a0, uint32_t a1, uint32_t a2, uint32_t a3,
                                         uint32_t b0, uint32_t b1) {
    asm volatile("mma.sync.aligned.m16n8k8.row.col.f32.tf32.tf32.f32 "
                 "{%0,%1,%2,%3}, {%4,%5,%6,%7}, {%8,%9}, {%0,%1,%2,%3};"
                 : "+f"(c0), "+f"(c1), "+f"(c2), "+f"(c3)
                 : "r"(a0), "r"(a1), "r"(a2), "r"(a3), "r"(b0), "r"(b1));
}

template <bool RELU>
__global__ __launch_bounds__(256) void linear_mma(
    const float4* __restrict__ hin4, const float4* __restrict__ agg4,
    const float* __restrict__ W, const float* __restrict__ bias,
    float* __restrict__ out, int n)
{
    __shared__ float As[64 * A_STRIDE];   // 33.8 KB

    int tid = threadIdx.x;
    int wid = tid >> 5, lane = tid & 31;
    int g = lane >> 2, tg = lane & 3;
    int wrow = (wid >> 2) * 32;
    int wcol = (wid & 3) * 16;

    uint32_t Bf[2][16][2];
    #pragma unroll
    for (int t = 0; t < 2; t++) {
        int ncol = wcol + t * 8 + g;
        #pragma unroll
        for (int s = 0; s < 16; s++) {
            Bf[t][s][0] = cvt_tf32(__ldg(&W[(s * 8 + 2 * tg)     * 64 + ncol]));
            Bf[t][s][1] = cvt_tf32(__ldg(&W[(s * 8 + 2 * tg + 1) * 64 + ncol]));
        }
    }
    float bs0[2], bs1[2];
    #pragma unroll
    for (int t = 0; t < 2; t++) {
        bs0[t] = __ldg(&bias[wcol + t * 8 + 2 * tg]);
        bs1[t] = __ldg(&bias[wcol + t * 8 + 2 * tg + 1]);
    }

    int ntiles = (n + 63) >> 6;
    for (int tile = blockIdx.x; tile < ntiles; tile += gridDim.x) {
        __syncthreads();
        #pragma unroll
        for (int r = 0; r < 8; r++) {
            int idx = tid + 256 * r;
            int row = idx >> 5, q = idx & 31;
            int node = tile * 64 + row;
            float4 v = make_float4(0.f, 0.f, 0.f, 0.f);
            if (node < n)
                v = (q < 16) ? __ldg(&hin4[(size_t)node * 16 + q])
                             : __ldg(&agg4[(size_t)node * 16 + q - 16]);
            uint32_t c0 = cvt_tf32(v.x), c1 = cvt_tf32(v.y);
            uint32_t c2 = cvt_tf32(v.z), c3 = cvt_tf32(v.w);
            uint4* p = reinterpret_cast<uint4*>(&As[row * A_STRIDE + q * 4]);
            *p = make_uint4(c0, c1, c2, c3);
        }
        __syncthreads();

        float c0[2][2], c1[2][2], c2[2][2], c3[2][2];
        #pragma unroll
        for (int m = 0; m < 2; m++)
            #pragma unroll
            for (int t = 0; t < 2; t++) {
                c0[m][t] = bs0[t]; c1[m][t] = bs1[t];
                c2[m][t] = bs0[t]; c3[m][t] = bs1[t];
            }

        #pragma unroll
        for (int s = 0; s < 16; s++) {
            int col = s * 8 + 2 * tg;
            #pragma unroll
            for (int m = 0; m < 2; m++) {
                int r0 = wrow + m * 16 + g;
                uint2 lo = *reinterpret_cast<const uint2*>(&As[r0 * A_STRIDE + col]);
                uint2 hi = *reinterpret_cast<const uint2*>(&As[(r0 + 8) * A_STRIDE + col]);
                #pragma unroll
                for (int t = 0; t < 2; t++)
                    mma_tf32(c0[m][t], c1[m][t], c2[m][t], c3[m][t],
                             lo.x, hi.x, lo.y, hi.y, Bf[t][s][0], Bf[t][s][1]);
            }
        }

        #pragma unroll
        for (int m = 0; m < 2; m++) {
            int row0 = tile * 64 + wrow + m * 16 + g;
            #pragma unroll
            for (int t = 0; t < 2; t++) {
                int col = wcol + t * 8 + 2 * tg;
                float2 lo = make_float2(c0[m][t], c1[m][t]);
                float2 hi = make_float2(c2[m][t], c3[m][t]);
                if (RELU) {
                    lo.x = fmaxf(lo.x, 0.f); lo.y = fmaxf(lo.y, 0.f);
                    hi.x = fmaxf(hi.x, 0.f); hi.y = fmaxf(hi.y, 0.f);
                }
                if (row0 < n)
                    *reinterpret_cast<float2*>(&out[(size_t)row0 * 64 + col]) = lo;
                if (row0 + 8 < n)
                    *reinterpret_cast<float2*>(&out[(size_t)(row0 + 8) * 64 + col]) = hi;
            }
        }
    }
}

// ---------------------------------------------------------------------------
extern "C" void kernel_launch(void* const* d_in, const int* in_sizes, int n_in,
                              void* d_out, int out_size) {
    const float* x  = (const float*)d_in[0];          // [N, 64]
    const int*   ei = (const int*)d_in[1];            // [2, E]
    const float* W0 = (const float*)d_in[2];          // [128, 64]
    const float* b0 = (const float*)d_in[3];          // [64]
    const float* W1 = (const float*)d_in[4];          // [128, 64]
    const float* b1 = (const float*)d_in[5];          // [64]
    float*       out = (float*)d_out;                 // [N, 64]

    int n = in_sizes[0] / D;
    int e = in_sizes[1] / 2;
    const int* src = ei;
    const int* dst = ei + e;

    float* hbuf;
    float* aggbuf;
    void*  degp;
    cudaGetSymbolAddress((void**)&hbuf, g_h);
    cudaGetSymbolAddress((void**)&aggbuf, g_agg);
    cudaGetSymbolAddress(&degp, g_deg);

    // --- CSR build ---
    cudaMemsetAsync(degp, 0, (size_t)n * sizeof(int));
    deg_kernel<<<((e + 7) / 8 + 255) / 256, 256>>>(dst, e);
    int nb = (n + 2047) / 2048;
    scan_sum<<<nb, 256>>>(n);
    scan_apply<<<nb, 256>>>(nb, n, e);
    fill_kernel<<<((e + 7) / 8 + 255) / 256, 256>>>(src, dst, e);

    int ntiles = (n + 63) / 64;
    int grid = (ntiles + 1) / 2;          // every block does exactly 2 tiles
    int agrid = (n + 15) / 16;            // 2 nodes/warp, 8 warps/block

    // --- Layer 0 ---
    agg_kernel<<<agrid, 256>>>((const float4*)x, n);
    linear_mma<true><<<grid, 256>>>(
        (const float4*)x, (const float4*)aggbuf, W0, b0, hbuf, n);

    // --- Layer 1 ---
    agg_kernel<<<agrid, 256>>>((const float4*)hbuf, n);
    linear_mma<false><<<grid, 256>>>(
        (const float4*)hbuf, (const float4*)aggbuf, W1, b1, out, n);
}